// round 12
// baseline (speedup 1.0000x reference)
#include <cuda_runtime.h>
#include <cstdint>

using ull = unsigned long long;

// ---- all weights in one constant struct (single memcpy node) ----
struct ConstW {
    ull pWq[72];   // [e][p] = (Wq[2p][e], Wq[2p+1][e])
    ull pWk[72];
    ull pWv[72];
    ull pWo[72];
    ull pW1[144];  // [e][p] p<12
    ull pW2[144];  // [f][p] p<6
    ull pbq[6], pbk[6], pbv[6], pbo[6], pb2[6], pb1[12];
};

__constant__ ConstW cw;
__device__ ConstW gStage;

namespace {

constexpr int N = 8;
constexpr int D = 12;
constexpr int F = 24;
constexpr int V = 128;
constexpr int WARPS = 8;
constexpr int THREADS = WARPS * 32;
constexpr int ITEMS_PER_BLOCK = 32;   // 4 items per warp
constexpr int XFW = 24;               // xf row width: 12 duplicated pairs

#define F4C(p) (*reinterpret_cast<const float4*>(p))
#define F4(p)  (*reinterpret_cast<float4*>(p))

__device__ __forceinline__ ull pack2(float x, float y) {
    ull p; asm("mov.b64 %0, {%1, %2};" : "=l"(p) : "f"(x), "f"(y)); return p;
}
__device__ __forceinline__ void unpack2(ull p, float& x, float& y) {
    asm("mov.b64 {%0, %1}, %2;" : "=f"(x), "=f"(y) : "l"(p));
}
__device__ __forceinline__ void ffma2(ull& d, ull a, ull b) {
    asm("fma.rn.f32x2 %0, %1, %2, %0;" : "+l"(d) : "l"(a), "l"(b));
}

// ---- pack kernel: gather 12 weight buffers into pair-major staging ----
__global__ void pack_weights_kernel(
    const float* __restrict__ Wq, const float* __restrict__ bq,
    const float* __restrict__ Wk, const float* __restrict__ bk,
    const float* __restrict__ Wv, const float* __restrict__ bv,
    const float* __restrict__ Wo, const float* __restrict__ bo,
    const float* __restrict__ W1, const float* __restrict__ b1,
    const float* __restrict__ W2, const float* __restrict__ b2)
{
    const int t = threadIdx.x;
    for (int i = t; i < 72; i += 256) {
        int e = i / 6, p = i % 6;
        gStage.pWq[i] = pack2(Wq[(2*p) * D + e], Wq[(2*p+1) * D + e]);
        gStage.pWk[i] = pack2(Wk[(2*p) * D + e], Wk[(2*p+1) * D + e]);
        gStage.pWv[i] = pack2(Wv[(2*p) * D + e], Wv[(2*p+1) * D + e]);
        gStage.pWo[i] = pack2(Wo[(2*p) * D + e], Wo[(2*p+1) * D + e]);
    }
    for (int i = t; i < 144; i += 256) {
        int e = i / 12, p = i % 12;
        gStage.pW1[i] = pack2(W1[(2*p) * D + e], W1[(2*p+1) * D + e]);
    }
    for (int i = t; i < 144; i += 256) {
        int f = i / 6, p = i % 6;
        gStage.pW2[i] = pack2(W2[(2*p) * F + f], W2[(2*p+1) * F + f]);
    }
    if (t < 6) {
        gStage.pbq[t] = pack2(bq[2*t], bq[2*t+1]);
        gStage.pbk[t] = pack2(bk[2*t], bk[2*t+1]);
        gStage.pbv[t] = pack2(bv[2*t], bv[2*t+1]);
        gStage.pbo[t] = pack2(bo[2*t], bo[2*t+1]);
        gStage.pb2[t] = pack2(b2[2*t], b2[2*t+1]);
    }
    if (t < 12) gStage.pb1[t] = pack2(b1[2*t], b1[2*t+1]);
}

__global__ __launch_bounds__(THREADS, 4)
void tiny_transformer_kernel(
    const int*   __restrict__ x,
    const float* __restrict__ embed,
    const float* __restrict__ pos,
    const float* __restrict__ blm,
    float* __restrict__ out)
{
    // ---- shared: only lane-divergent data ----
    __shared__ __align__(16) float sEmbT[D * V];   // transposed [d][v] for logits
    __shared__ __align__(16) float sPos[N * D];
    __shared__ __align__(16) float sBlm[V];
    // final X, stored as duplicated f32x2 pairs: row r = [x0,x0,x1,x1,...,x11,x11]
    __shared__ __align__(16) float sXf[WARPS][4 * N * XFW];

    const int tid = threadIdx.x;

    for (int i = tid; i < D * V; i += THREADS) {
        int d = i >> 7, v = i & 127;
        sEmbT[i] = embed[v * D + d];
    }
    for (int i = tid; i < N * D; i += THREADS) sPos[i] = pos[i];
    for (int i = tid; i < V; i += THREADS) sBlm[i] = blm[i];
    __syncthreads();

    const int w    = tid >> 5;
    const int lane = tid & 31;
    const int n    = lane & 7;
    const int item_base = blockIdx.x * ITEMS_PER_BLOCK + w * 4;

    // ---- phase 1: X = embed[x] + pos (gmem gather; embed is L2/L1-hot) ----
    const int tok = __ldg(&x[item_base * N + lane]);
    float X[D];
    {
        const float4* e4 = reinterpret_cast<const float4*>(embed);
        #pragma unroll
        for (int c = 0; c < 3; c++) {
            float4 e = __ldg(&e4[tok * 3 + c]);
            float4 p = F4C(&sPos[n * D + 4 * c]);
            X[4*c+0] = e.x + p.x; X[4*c+1] = e.y + p.y;
            X[4*c+2] = e.z + p.z; X[4*c+3] = e.w + p.w;
        }
    }

    // ---- phase 2: Q,K,V (packed FFMA2 against constant port) ----
    float Qr[D], Kr[D], Vr[D];
    {
        ull q2[6], k2[6], v2[6];
        #pragma unroll
        for (int p = 0; p < 6; p++) {
            q2[p] = cw.pbq[p]; k2[p] = cw.pbk[p]; v2[p] = cw.pbv[p];
        }
        #pragma unroll
        for (int e = 0; e < D; e++) {
            const ull xp = pack2(X[e], X[e]);
            #pragma unroll
            for (int p = 0; p < 6; p++) {
                ffma2(q2[p], xp, cw.pWq[e * 6 + p]);
                ffma2(k2[p], xp, cw.pWk[e * 6 + p]);
                ffma2(v2[p], xp, cw.pWv[e * 6 + p]);
            }
        }
        #pragma unroll
        for (int p = 0; p < 6; p++) {
            unpack2(q2[p], Qr[2*p], Qr[2*p+1]);
            unpack2(k2[p], Kr[2*p], Kr[2*p+1]);
            unpack2(v2[p], Vr[2*p], Vr[2*p+1]);
        }
    }

    // ---- phase 3: scores via width-8 shuffles ----
    float S[N];
    {
        const float inv_scale = 0.28867513459481287f;  // 1/sqrt(12)
        #pragma unroll
        for (int m = 0; m < N; m++) {
            float acc = 0.f;
            #pragma unroll
            for (int e = 0; e < D; e++)
                acc += Qr[e] * __shfl_sync(0xffffffffu, Kr[e], m, 8);
            S[m] = (m <= n) ? acc * inv_scale : -1e30f;
        }
    }

    // ---- phase 4: softmax ----
    {
        float mx = S[0];
        #pragma unroll
        for (int m = 1; m < N; m++) mx = fmaxf(mx, S[m]);
        float sum = 0.f;
        #pragma unroll
        for (int m = 0; m < N; m++) { S[m] = __expf(S[m] - mx); sum += S[m]; }
        const float inv = 1.f / sum;
        #pragma unroll
        for (int m = 0; m < N; m++) S[m] *= inv;
    }

    // ---- phase 5: A = softmax @ V via shuffles ----
    float A[D];
    #pragma unroll
    for (int e = 0; e < D; e++) A[e] = 0.f;
    #pragma unroll
    for (int m = 0; m < N; m++) {
        const float s = S[m];
        #pragma unroll
        for (int e = 0; e < D; e++)
            A[e] += s * __shfl_sync(0xffffffffu, Vr[e], m, 8);
    }

    // ---- phase 6: X += A @ Wo^T + bo (packed) ----
    {
        ull o2[6];
        #pragma unroll
        for (int p = 0; p < 6; p++) o2[p] = cw.pbo[p];
        #pragma unroll
        for (int e = 0; e < D; e++) {
            const ull ap = pack2(A[e], A[e]);
            #pragma unroll
            for (int p = 0; p < 6; p++)
                ffma2(o2[p], ap, cw.pWo[e * 6 + p]);
        }
        #pragma unroll
        for (int p = 0; p < 6; p++) {
            float u, v; unpack2(o2[p], u, v);
            X[2*p] += u; X[2*p+1] += v;
        }
    }

    // ---- phase 7: H = relu(X @ W1^T + b1) (packed) ----
    float H[F];
    {
        ull h2[12];
        #pragma unroll
        for (int p = 0; p < 12; p++) h2[p] = cw.pb1[p];
        #pragma unroll
        for (int e = 0; e < D; e++) {
            const ull xp = pack2(X[e], X[e]);
            #pragma unroll
            for (int p = 0; p < 12; p++)
                ffma2(h2[p], xp, cw.pW1[e * 12 + p]);
        }
        #pragma unroll
        for (int p = 0; p < 12; p++) {
            float u, v; unpack2(h2[p], u, v);
            H[2*p]   = fmaxf(u, 0.f);
            H[2*p+1] = fmaxf(v, 0.f);
        }
    }

    // ---- phase 8: X += H @ W2^T + b2 (packed) ----
    {
        ull x2[6];
        #pragma unroll
        for (int p = 0; p < 6; p++) x2[p] = cw.pb2[p];
        #pragma unroll
        for (int f = 0; f < F; f++) {
            const ull hp = pack2(H[f], H[f]);
            #pragma unroll
            for (int p = 0; p < 6; p++)
                ffma2(x2[p], hp, cw.pW2[f * 6 + p]);
        }
        #pragma unroll
        for (int p = 0; p < 6; p++) {
            float u, v; unpack2(x2[p], u, v);
            X[2*p] += u; X[2*p+1] += v;
        }
    }

    // ---- hand off final X as DUPLICATED f32x2 pairs ----
    // row layout: [x0,x0,x1,x1, x2,x2,x3,x3, ..., x11,x11]  (24 floats)
    {
        float* dst = &sXf[w][lane * XFW];
        F4(dst)      = make_float4(X[0],  X[0],  X[1],  X[1]);
        F4(dst + 4)  = make_float4(X[2],  X[2],  X[3],  X[3]);
        F4(dst + 8)  = make_float4(X[4],  X[4],  X[5],  X[5]);
        F4(dst + 12) = make_float4(X[6],  X[6],  X[7],  X[7]);
        F4(dst + 16) = make_float4(X[8],  X[8],  X[9],  X[9]);
        F4(dst + 20) = make_float4(X[10], X[10], X[11], X[11]);
    }
    __syncwarp();

    // ---- phase 9: logits = Xf @ embed^T + b_lm ----
    // two column-half passes; 12 packed embT regs per pass; per row:
    // 6 broadcast LDS.128 yield 12 ready-packed (x,x) operands -> 12 FFMA2.
    {
        const ulonglong2* xf2 = reinterpret_cast<const ulonglong2*>(sXf[w]);
        float* obase = out + (size_t)item_base * (N * V);

        #pragma unroll
        for (int pass = 0; pass < 2; pass++) {
            const int v0 = lane * 2 + pass * 64;
            ull e2[D];
            #pragma unroll
            for (int d = 0; d < D; d++) {
                const float2 e = *reinterpret_cast<const float2*>(&sEmbT[d * V + v0]);
                e2[d] = pack2(e.x, e.y);
            }
            const float2 bl = *reinterpret_cast<const float2*>(&sBlm[v0]);
            const ull bl2 = pack2(bl.x, bl.y);

            #pragma unroll 2
            for (int r = 0; r < 4 * N; r++) {
                const ulonglong2* row = xf2 + r * 6;
                ulonglong2 p0 = row[0], p1 = row[1], p2 = row[2];
                ulonglong2 p3 = row[3], p4 = row[4], p5 = row[5];
                ull acc = bl2;
                ffma2(acc, p0.x, e2[0]);  ffma2(acc, p0.y, e2[1]);
                ffma2(acc, p1.x, e2[2]);  ffma2(acc, p1.y, e2[3]);
                ffma2(acc, p2.x, e2[4]);  ffma2(acc, p2.y, e2[5]);
                ffma2(acc, p3.x, e2[6]);  ffma2(acc, p3.y, e2[7]);
                ffma2(acc, p4.x, e2[8]);  ffma2(acc, p4.y, e2[9]);
                ffma2(acc, p5.x, e2[10]); ffma2(acc, p5.y, e2[11]);
                float u, v; unpack2(acc, u, v);
                *reinterpret_cast<float2*>(&obase[(size_t)r * V + v0]) =
                    make_float2(u, v);            // warp: 256B contiguous
            }
        }
    }
}

}  // namespace

extern "C" void kernel_launch(void* const* d_in, const int* in_sizes, int n_in,
                              void* d_out, int out_size)
{
    const int*   x     = (const int*)  d_in[0];
    const float* embed = (const float*)d_in[1];
    const float* pos   = (const float*)d_in[2];
    const float* blm   = (const float*)d_in[15];
    float* out = (float*)d_out;

    // 1) gather + pair-pack all weights into staging (one kernel node)
    pack_weights_kernel<<<1, 256>>>(
        (const float*)d_in[3],  (const float*)d_in[4],
        (const float*)d_in[5],  (const float*)d_in[6],
        (const float*)d_in[7],  (const float*)d_in[8],
        (const float*)d_in[9],  (const float*)d_in[10],
        (const float*)d_in[11], (const float*)d_in[12],
        (const float*)d_in[13], (const float*)d_in[14]);

    // 2) one D2D copy staging -> constant bank (one memcpy node)
    void *dstC, *srcG;
    cudaGetSymbolAddress(&dstC, cw);
    cudaGetSymbolAddress(&srcG, gStage);
    cudaMemcpyAsync(dstC, srcG, sizeof(ConstW), cudaMemcpyDeviceToDevice);

    // 3) main kernel
    const int batch  = in_sizes[0] / N;              // 32768
    const int blocks = batch / ITEMS_PER_BLOCK;      // 1024

    tiny_transformer_kernel<<<blocks, THREADS>>>(x, embed, pos, blm, out);
}

// round 13
// speedup vs baseline: 1.1905x; 1.1905x over previous
#include <cuda_runtime.h>
#include <cstdint>

using ull = unsigned long long;

// ---- all weights in one constant struct ----
struct ConstW {
    ull pWq[72];   // [e][p] = (Wq[2p][e], Wq[2p+1][e])
    ull pWk[72];
    ull pWv[72];
    ull pWo[72];
    ull pW1[144];  // [e][p] p<12
    ull pW2[144];  // [f][p] p<6
    ull pbq[6], pbk[6], pbv[6], pbo[6], pb2[6], pb1[12];
};

__constant__ ConstW cw;

namespace {

constexpr int N = 8;
constexpr int D = 12;
constexpr int F = 24;
constexpr int V = 128;
constexpr int WARPS = 8;
constexpr int THREADS = WARPS * 32;
constexpr int ITEMS_PER_BLOCK = 32;   // 4 items per warp

#define F4C(p) (*reinterpret_cast<const float4*>(p))
#define F4(p)  (*reinterpret_cast<float4*>(p))

__device__ __forceinline__ ull pack2(float x, float y) {
    ull p; asm("mov.b64 %0, {%1, %2};" : "=l"(p) : "f"(x), "f"(y)); return p;
}
__device__ __forceinline__ void unpack2(ull p, float& x, float& y) {
    asm("mov.b64 {%0, %1}, %2;" : "=f"(x), "=f"(y) : "l"(p));
}
__device__ __forceinline__ void ffma2(ull& d, ull a, ull b) {
    asm("fma.rn.f32x2 %0, %1, %2, %0;" : "+l"(d) : "l"(a), "l"(b));
}

// ---- pack kernel: gather 12 weight buffers, pair-pack, write straight
//      into the constant bank (dst = symbol address of cw) ----
__global__ void pack_weights_kernel(
    ConstW* __restrict__ dst,
    const float* __restrict__ Wq, const float* __restrict__ bq,
    const float* __restrict__ Wk, const float* __restrict__ bk,
    const float* __restrict__ Wv, const float* __restrict__ bv,
    const float* __restrict__ Wo, const float* __restrict__ bo,
    const float* __restrict__ W1, const float* __restrict__ b1,
    const float* __restrict__ W2, const float* __restrict__ b2)
{
    const int t = threadIdx.x;
    for (int i = t; i < 72; i += 256) {
        int e = i / 6, p = i % 6;
        dst->pWq[i] = pack2(Wq[(2*p) * D + e], Wq[(2*p+1) * D + e]);
        dst->pWk[i] = pack2(Wk[(2*p) * D + e], Wk[(2*p+1) * D + e]);
        dst->pWv[i] = pack2(Wv[(2*p) * D + e], Wv[(2*p+1) * D + e]);
        dst->pWo[i] = pack2(Wo[(2*p) * D + e], Wo[(2*p+1) * D + e]);
    }
    for (int i = t; i < 144; i += 256) {
        int e = i / 12, p = i % 12;
        dst->pW1[i] = pack2(W1[(2*p) * D + e], W1[(2*p+1) * D + e]);
    }
    for (int i = t; i < 144; i += 256) {
        int f = i / 6, p = i % 6;
        dst->pW2[i] = pack2(W2[(2*p) * F + f], W2[(2*p+1) * F + f]);
    }
    if (t < 6) {
        dst->pbq[t] = pack2(bq[2*t], bq[2*t+1]);
        dst->pbk[t] = pack2(bk[2*t], bk[2*t+1]);
        dst->pbv[t] = pack2(bv[2*t], bv[2*t+1]);
        dst->pbo[t] = pack2(bo[2*t], bo[2*t+1]);
        dst->pb2[t] = pack2(b2[2*t], b2[2*t+1]);
    }
    if (t < 12) dst->pb1[t] = pack2(b1[2*t], b1[2*t+1]);
}

__global__ __launch_bounds__(THREADS, 3)
void tiny_transformer_kernel(
    const int*   __restrict__ x,
    const float* __restrict__ embed,
    const float* __restrict__ pos,
    const float* __restrict__ blm,
    float* __restrict__ out)
{
    // ---- shared: only lane-divergent data ----
    __shared__ __align__(16) float sEmbT[D * V];   // transposed [d][v] for logits
    __shared__ __align__(16) float sPos[N * D];
    __shared__ __align__(16) float sBlm[V];
    __shared__ __align__(16) float sXf[WARPS][4 * N * D];

    const int tid = threadIdx.x;

    for (int i = tid; i < D * V; i += THREADS) {
        int d = i >> 7, v = i & 127;
        sEmbT[i] = embed[v * D + d];
    }
    for (int i = tid; i < N * D; i += THREADS) sPos[i] = pos[i];
    for (int i = tid; i < V; i += THREADS) sBlm[i] = blm[i];
    __syncthreads();

    const int w    = tid >> 5;
    const int lane = tid & 31;
    const int n    = lane & 7;
    const int item_base = blockIdx.x * ITEMS_PER_BLOCK + w * 4;

    // ---- phase 1: X = embed[x] + pos (gmem gather; embed is L2/L1-hot) ----
    const int tok = __ldg(&x[item_base * N + lane]);
    float X[D];
    {
        const float4* e4 = reinterpret_cast<const float4*>(embed);
        #pragma unroll
        for (int c = 0; c < 3; c++) {
            float4 e = __ldg(&e4[tok * 3 + c]);
            float4 p = F4C(&sPos[n * D + 4 * c]);
            X[4*c+0] = e.x + p.x; X[4*c+1] = e.y + p.y;
            X[4*c+2] = e.z + p.z; X[4*c+3] = e.w + p.w;
        }
    }

    // ---- phase 2: Q,K,V (packed FFMA2 against constant port) ----
    float Qr[D], Kr[D], Vr[D];
    {
        ull q2[6], k2[6], v2[6];
        #pragma unroll
        for (int p = 0; p < 6; p++) {
            q2[p] = cw.pbq[p]; k2[p] = cw.pbk[p]; v2[p] = cw.pbv[p];
        }
        #pragma unroll
        for (int e = 0; e < D; e++) {
            const ull xp = pack2(X[e], X[e]);
            #pragma unroll
            for (int p = 0; p < 6; p++) {
                ffma2(q2[p], xp, cw.pWq[e * 6 + p]);
                ffma2(k2[p], xp, cw.pWk[e * 6 + p]);
                ffma2(v2[p], xp, cw.pWv[e * 6 + p]);
            }
        }
        #pragma unroll
        for (int p = 0; p < 6; p++) {
            unpack2(q2[p], Qr[2*p], Qr[2*p+1]);
            unpack2(k2[p], Kr[2*p], Kr[2*p+1]);
            unpack2(v2[p], Vr[2*p], Vr[2*p+1]);
        }
    }

    // ---- phase 3: scores via width-8 shuffles ----
    float S[N];
    {
        const float inv_scale = 0.28867513459481287f;  // 1/sqrt(12)
        #pragma unroll
        for (int m = 0; m < N; m++) {
            float acc = 0.f;
            #pragma unroll
            for (int e = 0; e < D; e++)
                acc += Qr[e] * __shfl_sync(0xffffffffu, Kr[e], m, 8);
            S[m] = (m <= n) ? acc * inv_scale : -1e30f;
        }
    }

    // ---- phase 4: softmax ----
    {
        float mx = S[0];
        #pragma unroll
        for (int m = 1; m < N; m++) mx = fmaxf(mx, S[m]);
        float sum = 0.f;
        #pragma unroll
        for (int m = 0; m < N; m++) { S[m] = __expf(S[m] - mx); sum += S[m]; }
        const float inv = 1.f / sum;
        #pragma unroll
        for (int m = 0; m < N; m++) S[m] *= inv;
    }

    // ---- phase 5: A = softmax @ V via shuffles ----
    float A[D];
    #pragma unroll
    for (int e = 0; e < D; e++) A[e] = 0.f;
    #pragma unroll
    for (int m = 0; m < N; m++) {
        const float s = S[m];
        #pragma unroll
        for (int e = 0; e < D; e++)
            A[e] += s * __shfl_sync(0xffffffffu, Vr[e], m, 8);
    }

    // ---- phase 6: X += A @ Wo^T + bo (packed) ----
    {
        ull o2[6];
        #pragma unroll
        for (int p = 0; p < 6; p++) o2[p] = cw.pbo[p];
        #pragma unroll
        for (int e = 0; e < D; e++) {
            const ull ap = pack2(A[e], A[e]);
            #pragma unroll
            for (int p = 0; p < 6; p++)
                ffma2(o2[p], ap, cw.pWo[e * 6 + p]);
        }
        #pragma unroll
        for (int p = 0; p < 6; p++) {
            float u, v; unpack2(o2[p], u, v);
            X[2*p] += u; X[2*p+1] += v;
        }
    }

    // ---- phase 7: H = relu(X @ W1^T + b1) (packed) ----
    float H[F];
    {
        ull h2[12];
        #pragma unroll
        for (int p = 0; p < 12; p++) h2[p] = cw.pb1[p];
        #pragma unroll
        for (int e = 0; e < D; e++) {
            const ull xp = pack2(X[e], X[e]);
            #pragma unroll
            for (int p = 0; p < 12; p++)
                ffma2(h2[p], xp, cw.pW1[e * 12 + p]);
        }
        #pragma unroll
        for (int p = 0; p < 12; p++) {
            float u, v; unpack2(h2[p], u, v);
            H[2*p]   = fmaxf(u, 0.f);
            H[2*p+1] = fmaxf(v, 0.f);
        }
    }

    // ---- phase 8: X += H @ W2^T + b2 (packed) ----
    {
        ull x2[6];
        #pragma unroll
        for (int p = 0; p < 6; p++) x2[p] = cw.pb2[p];
        #pragma unroll
        for (int f = 0; f < F; f++) {
            const ull hp = pack2(H[f], H[f]);
            #pragma unroll
            for (int p = 0; p < 6; p++)
                ffma2(x2[p], hp, cw.pW2[f * 6 + p]);
        }
        #pragma unroll
        for (int p = 0; p < 6; p++) {
            float u, v; unpack2(x2[p], u, v);
            X[2*p] += u; X[2*p+1] += v;
        }
    }

    // ---- hand off final X ----
    {
        float* dst = &sXf[w][lane * D];
        F4(dst)     = make_float4(X[0], X[1], X[2],  X[3]);
        F4(dst + 4) = make_float4(X[4], X[5], X[6],  X[7]);
        F4(dst + 8) = make_float4(X[8], X[9], X[10], X[11]);
    }
    __syncwarp();

    // ---- phase 9: logits = Xf @ embed^T + b_lm (single pass, 4 cols/lane) ----
    // embT cached once in 48 regs, amortized over 32 rows: per row just
    // 3 broadcast LDS.128 + 12 packs + 24 FFMA2 + 1 STG.128.
    {
        const int v0 = lane * 4;
        ull e01[D], e23[D];
        #pragma unroll
        for (int d = 0; d < D; d++) {
            float4 e = F4C(&sEmbT[d * V + v0]);
            e01[d] = pack2(e.x, e.y);
            e23[d] = pack2(e.z, e.w);
        }
        const float4 bl = F4C(&sBlm[v0]);
        const ull bl01 = pack2(bl.x, bl.y);
        const ull bl23 = pack2(bl.z, bl.w);

        float* obase = out + (size_t)item_base * (N * V) + v0;
        const float* xf = sXf[w];

        for (int r = 0; r < 4 * N; r++) {
            float4 xa = F4C(&xf[r * D]);       // broadcast reads
            float4 xb = F4C(&xf[r * D + 4]);
            float4 xc = F4C(&xf[r * D + 8]);
            const float xr[D] = {xa.x, xa.y, xa.z, xa.w,
                                 xb.x, xb.y, xb.z, xb.w,
                                 xc.x, xc.y, xc.z, xc.w};
            ull a01 = bl01, a23 = bl23;
            #pragma unroll
            for (int d = 0; d < D; d++) {
                const ull xv2 = pack2(xr[d], xr[d]);
                ffma2(a01, xv2, e01[d]);
                ffma2(a23, xv2, e23[d]);
            }
            float4 acc;
            unpack2(a01, acc.x, acc.y);
            unpack2(a23, acc.z, acc.w);
            F4(&obase[(size_t)r * V]) = acc;   // coalesced 512B per warp-row
        }
    }
}

}  // namespace

extern "C" void kernel_launch(void* const* d_in, const int* in_sizes, int n_in,
                              void* d_out, int out_size)
{
    const int*   x     = (const int*)  d_in[0];
    const float* embed = (const float*)d_in[1];
    const float* pos   = (const float*)d_in[2];
    const float* blm   = (const float*)d_in[15];
    float* out = (float*)d_out;

    // symbol address query (host-side, not a captured op)
    void* cwAddr = nullptr;
    cudaGetSymbolAddress(&cwAddr, cw);

    // 1) gather + pair-pack all weights DIRECTLY into the constant bank
    //    (constant caches invalidate at the next kernel-launch boundary)
    pack_weights_kernel<<<1, 256>>>(
        (ConstW*)cwAddr,
        (const float*)d_in[3],  (const float*)d_in[4],
        (const float*)d_in[5],  (const float*)d_in[6],
        (const float*)d_in[7],  (const float*)d_in[8],
        (const float*)d_in[9],  (const float*)d_in[10],
        (const float*)d_in[11], (const float*)d_in[12],
        (const float*)d_in[13], (const float*)d_in[14]);

    // 2) main kernel
    const int batch  = in_sizes[0] / N;              // 32768
    const int blocks = batch / ITEMS_PER_BLOCK;      // 1024

    tiny_transformer_kernel<<<blocks, THREADS>>>(x, embed, pos, blm, out);
}

// round 14
// speedup vs baseline: 1.2510x; 1.0508x over previous
#include <cuda_runtime.h>
#include <cstdint>

using ull = unsigned long long;

// ---- all weights in one constant struct ----
struct ConstW {
    ull pWq[72];   // [e][p] = (Wq[2p][e], Wq[2p+1][e])
    ull pWk[72];
    ull pWv[72];
    ull pWo[72];
    ull pW1[144];  // [e][p] p<12
    ull pW2[144];  // [f][p] p<6
    ull pbq[6], pbk[6], pbv[6], pbo[6], pb2[6], pb1[12];
};

__constant__ ConstW cw;

namespace {

constexpr int N = 8;
constexpr int D = 12;
constexpr int F = 24;
constexpr int V = 128;
constexpr int WARPS = 8;
constexpr int THREADS = WARPS * 32;
constexpr int ITEMS_PER_BLOCK = 32;   // 4 items per warp
constexpr int IST = 100;              // K/V item stride in floats (bank-stagger +4/group)
constexpr int SCR = 800;              // per-warp scratch floats (K:0..400, V:400..800)

#define F4C(p) (*reinterpret_cast<const float4*>(p))
#define F4(p)  (*reinterpret_cast<float4*>(p))

__device__ __forceinline__ ull pack2(float x, float y) {
    ull p; asm("mov.b64 %0, {%1, %2};" : "=l"(p) : "f"(x), "f"(y)); return p;
}
__device__ __forceinline__ void unpack2(ull p, float& x, float& y) {
    asm("mov.b64 {%0, %1}, %2;" : "=f"(x), "=f"(y) : "l"(p));
}
__device__ __forceinline__ void ffma2(ull& d, ull a, ull b) {
    asm("fma.rn.f32x2 %0, %1, %2, %0;" : "+l"(d) : "l"(a), "l"(b));
}

// ---- pack kernel: gather 12 weight buffers, pair-pack, write straight
//      into the constant bank (dst = symbol address of cw) ----
__global__ void pack_weights_kernel(
    ConstW* __restrict__ dst,
    const float* __restrict__ Wq, const float* __restrict__ bq,
    const float* __restrict__ Wk, const float* __restrict__ bk,
    const float* __restrict__ Wv, const float* __restrict__ bv,
    const float* __restrict__ Wo, const float* __restrict__ bo,
    const float* __restrict__ W1, const float* __restrict__ b1,
    const float* __restrict__ W2, const float* __restrict__ b2)
{
    const int t = threadIdx.x;
    for (int i = t; i < 72; i += 256) {
        int e = i / 6, p = i % 6;
        dst->pWq[i] = pack2(Wq[(2*p) * D + e], Wq[(2*p+1) * D + e]);
        dst->pWk[i] = pack2(Wk[(2*p) * D + e], Wk[(2*p+1) * D + e]);
        dst->pWv[i] = pack2(Wv[(2*p) * D + e], Wv[(2*p+1) * D + e]);
        dst->pWo[i] = pack2(Wo[(2*p) * D + e], Wo[(2*p+1) * D + e]);
    }
    for (int i = t; i < 144; i += 256) {
        int e = i / 12, p = i % 12;
        dst->pW1[i] = pack2(W1[(2*p) * D + e], W1[(2*p+1) * D + e]);
    }
    for (int i = t; i < 144; i += 256) {
        int f = i / 6, p = i % 6;
        dst->pW2[i] = pack2(W2[(2*p) * F + f], W2[(2*p+1) * F + f]);
    }
    if (t < 6) {
        dst->pbq[t] = pack2(bq[2*t], bq[2*t+1]);
        dst->pbk[t] = pack2(bk[2*t], bk[2*t+1]);
        dst->pbv[t] = pack2(bv[2*t], bv[2*t+1]);
        dst->pbo[t] = pack2(bo[2*t], bo[2*t+1]);
        dst->pb2[t] = pack2(b2[2*t], b2[2*t+1]);
    }
    if (t < 12) dst->pb1[t] = pack2(b1[2*t], b1[2*t+1]);
}

__global__ __launch_bounds__(THREADS, 3)
void tiny_transformer_kernel(
    const int*   __restrict__ x,
    const float* __restrict__ embed,
    const float* __restrict__ pos,
    const float* __restrict__ blm,
    float* __restrict__ out)
{
    // ---- shared ----
    __shared__ __align__(16) float sEmbT[D * V];   // transposed [d][v] for logits
    __shared__ __align__(16) float sPos[N * D];
    __shared__ __align__(16) float sBlm[V];
    // per-warp scratch: phases 3-5 hold K (0..400) and V (400..800);
    // after a syncwarp the low 384 floats are reused for final X (phase 9).
    __shared__ __align__(16) float sScr[WARPS][SCR];

    const int tid = threadIdx.x;

    for (int i = tid; i < D * V; i += THREADS) {
        int d = i >> 7, v = i & 127;
        sEmbT[i] = embed[v * D + d];
    }
    for (int i = tid; i < N * D; i += THREADS) sPos[i] = pos[i];
    for (int i = tid; i < V; i += THREADS) sBlm[i] = blm[i];
    __syncthreads();

    const int w    = tid >> 5;
    const int lane = tid & 31;
    const int n    = lane & 7;            // token within item
    const int g    = lane >> 3;           // item within warp
    const int item_base = blockIdx.x * ITEMS_PER_BLOCK + w * 4;

    // ---- phase 1: X = embed[x] + pos ----
    const int tok = __ldg(&x[item_base * N + lane]);
    float X[D];
    {
        const float4* e4 = reinterpret_cast<const float4*>(embed);
        #pragma unroll
        for (int c = 0; c < 3; c++) {
            float4 e = __ldg(&e4[tok * 3 + c]);
            float4 p = F4C(&sPos[n * D + 4 * c]);
            X[4*c+0] = e.x + p.x; X[4*c+1] = e.y + p.y;
            X[4*c+2] = e.z + p.z; X[4*c+3] = e.w + p.w;
        }
    }

    // ---- phase 2: Q,K,V (packed FFMA2 on constant port); K,V -> smem packed ----
    ull q2[6];
    {
        ull k2[6], v2[6];
        #pragma unroll
        for (int p = 0; p < 6; p++) {
            q2[p] = cw.pbq[p]; k2[p] = cw.pbk[p]; v2[p] = cw.pbv[p];
        }
        #pragma unroll
        for (int e = 0; e < D; e++) {
            const ull xp = pack2(X[e], X[e]);
            #pragma unroll
            for (int p = 0; p < 6; p++) {
                ffma2(q2[p], xp, cw.pWq[e * 6 + p]);
                ffma2(k2[p], xp, cw.pWk[e * 6 + p]);
                ffma2(v2[p], xp, cw.pWv[e * 6 + p]);
            }
        }
        // store K, V rows (natural float order) for group-broadcast reads
        ulonglong2* kd = reinterpret_cast<ulonglong2*>(&sScr[w][g * IST + n * D]);
        kd[0] = make_ulonglong2(k2[0], k2[1]);
        kd[1] = make_ulonglong2(k2[2], k2[3]);
        kd[2] = make_ulonglong2(k2[4], k2[5]);
        ulonglong2* vd = reinterpret_cast<ulonglong2*>(&sScr[w][400 + g * IST + n * D]);
        vd[0] = make_ulonglong2(v2[0], v2[1]);
        vd[1] = make_ulonglong2(v2[2], v2[3]);
        vd[2] = make_ulonglong2(v2[4], v2[5]);
    }
    __syncwarp();

    // ---- phase 3: scores S[n][m] = <Q_n, K_m>/sqrt(D) via packed smem rows ----
    float S[N];
    {
        const float inv_scale = 0.28867513459481287f;  // 1/sqrt(12)
        const ulonglong2* kb =
            reinterpret_cast<const ulonglong2*>(&sScr[w][g * IST]);
        #pragma unroll
        for (int m = 0; m < N; m++) {
            ulonglong2 r0 = kb[m * 3], r1 = kb[m * 3 + 1], r2 = kb[m * 3 + 2];
            ull acc = 0;
            ffma2(acc, q2[0], r0.x); ffma2(acc, q2[1], r0.y);
            ffma2(acc, q2[2], r1.x); ffma2(acc, q2[3], r1.y);
            ffma2(acc, q2[4], r2.x); ffma2(acc, q2[5], r2.y);
            float u, v; unpack2(acc, u, v);
            S[m] = (m <= n) ? (u + v) * inv_scale : -1e30f;
        }
    }

    // ---- phase 4: softmax ----
    {
        float mx = S[0];
        #pragma unroll
        for (int m = 1; m < N; m++) mx = fmaxf(mx, S[m]);
        float sum = 0.f;
        #pragma unroll
        for (int m = 0; m < N; m++) { S[m] = __expf(S[m] - mx); sum += S[m]; }
        const float inv = 1.f / sum;
        #pragma unroll
        for (int m = 0; m < N; m++) S[m] *= inv;
    }

    // ---- phase 5: A = softmax @ V via packed smem rows ----
    float A[D];
    {
        ull a2[6] = {0, 0, 0, 0, 0, 0};
        const ulonglong2* vb =
            reinterpret_cast<const ulonglong2*>(&sScr[w][400 + g * IST]);
        #pragma unroll
        for (int m = 0; m < N; m++) {
            const ull sp = pack2(S[m], S[m]);
            ulonglong2 r0 = vb[m * 3], r1 = vb[m * 3 + 1], r2 = vb[m * 3 + 2];
            ffma2(a2[0], sp, r0.x); ffma2(a2[1], sp, r0.y);
            ffma2(a2[2], sp, r1.x); ffma2(a2[3], sp, r1.y);
            ffma2(a2[4], sp, r2.x); ffma2(a2[5], sp, r2.y);
        }
        #pragma unroll
        for (int p = 0; p < 6; p++) unpack2(a2[p], A[2*p], A[2*p+1]);
    }

    // ---- phase 6: X += A @ Wo^T + bo (packed) ----
    {
        ull o2[6];
        #pragma unroll
        for (int p = 0; p < 6; p++) o2[p] = cw.pbo[p];
        #pragma unroll
        for (int e = 0; e < D; e++) {
            const ull ap = pack2(A[e], A[e]);
            #pragma unroll
            for (int p = 0; p < 6; p++)
                ffma2(o2[p], ap, cw.pWo[e * 6 + p]);
        }
        #pragma unroll
        for (int p = 0; p < 6; p++) {
            float u, v; unpack2(o2[p], u, v);
            X[2*p] += u; X[2*p+1] += v;
        }
    }

    // ---- phase 7: H = relu(X @ W1^T + b1) (packed) ----
    float H[F];
    {
        ull h2[12];
        #pragma unroll
        for (int p = 0; p < 12; p++) h2[p] = cw.pb1[p];
        #pragma unroll
        for (int e = 0; e < D; e++) {
            const ull xp = pack2(X[e], X[e]);
            #pragma unroll
            for (int p = 0; p < 12; p++)
                ffma2(h2[p], xp, cw.pW1[e * 12 + p]);
        }
        #pragma unroll
        for (int p = 0; p < 12; p++) {
            float u, v; unpack2(h2[p], u, v);
            H[2*p]   = fmaxf(u, 0.f);
            H[2*p+1] = fmaxf(v, 0.f);
        }
    }

    // ---- phase 8: X += H @ W2^T + b2 (packed) ----
    {
        ull x2[6];
        #pragma unroll
        for (int p = 0; p < 6; p++) x2[p] = cw.pb2[p];
        #pragma unroll
        for (int f = 0; f < F; f++) {
            const ull hp = pack2(H[f], H[f]);
            #pragma unroll
            for (int p = 0; p < 6; p++)
                ffma2(x2[p], hp, cw.pW2[f * 6 + p]);
        }
        #pragma unroll
        for (int p = 0; p < 6; p++) {
            float u, v; unpack2(x2[p], u, v);
            X[2*p] += u; X[2*p+1] += v;
        }
    }

    // ---- hand off final X (reuses K region of scratch; all lanes are
    //      past their V reads after this barrier) ----
    __syncwarp();
    {
        float* dst = &sScr[w][lane * D];
        F4(dst)     = make_float4(X[0], X[1], X[2],  X[3]);
        F4(dst + 4) = make_float4(X[4], X[5], X[6],  X[7]);
        F4(dst + 8) = make_float4(X[8], X[9], X[10], X[11]);
    }
    __syncwarp();

    // ---- phase 9: logits = Xf @ embed^T + b_lm (single pass, 4 cols/lane) ----
    {
        const int v0 = lane * 4;
        ull e01[D], e23[D];
        #pragma unroll
        for (int d = 0; d < D; d++) {
            float4 e = F4C(&sEmbT[d * V + v0]);
            e01[d] = pack2(e.x, e.y);
            e23[d] = pack2(e.z, e.w);
        }
        const float4 bl = F4C(&sBlm[v0]);
        const ull bl01 = pack2(bl.x, bl.y);
        const ull bl23 = pack2(bl.z, bl.w);

        float* obase = out + (size_t)item_base * (N * V) + v0;
        const float* xf = sScr[w];

        for (int r = 0; r < 4 * N; r++) {
            float4 xa = F4C(&xf[r * D]);       // broadcast reads
            float4 xb = F4C(&xf[r * D + 4]);
            float4 xc = F4C(&xf[r * D + 8]);
            const float xr[D] = {xa.x, xa.y, xa.z, xa.w,
                                 xb.x, xb.y, xb.z, xb.w,
                                 xc.x, xc.y, xc.z, xc.w};
            ull a01 = bl01, a23 = bl23;
            #pragma unroll
            for (int d = 0; d < D; d++) {
                const ull xv2 = pack2(xr[d], xr[d]);
                ffma2(a01, xv2, e01[d]);
                ffma2(a23, xv2, e23[d]);
            }
            float4 acc;
            unpack2(a01, acc.x, acc.y);
            unpack2(a23, acc.z, acc.w);
            F4(&obase[(size_t)r * V]) = acc;   // coalesced 512B per warp-row
        }
    }
}

}  // namespace

extern "C" void kernel_launch(void* const* d_in, const int* in_sizes, int n_in,
                              void* d_out, int out_size)
{
    const int*   x     = (const int*)  d_in[0];
    const float* embed = (const float*)d_in[1];
    const float* pos   = (const float*)d_in[2];
    const float* blm   = (const float*)d_in[15];
    float* out = (float*)d_out;

    // symbol address query (host-side, not a captured op)
    void* cwAddr = nullptr;
    cudaGetSymbolAddress(&cwAddr, cw);

    // 1) gather + pair-pack all weights DIRECTLY into the constant bank
    pack_weights_kernel<<<1, 256>>>(
        (ConstW*)cwAddr,
        (const float*)d_in[3],  (const float*)d_in[4],
        (const float*)d_in[5],  (const float*)d_in[6],
        (const float*)d_in[7],  (const float*)d_in[8],
        (const float*)d_in[9],  (const float*)d_in[10],
        (const float*)d_in[11], (const float*)d_in[12],
        (const float*)d_in[13], (const float*)d_in[14]);

    // 2) main kernel
    const int batch  = in_sizes[0] / N;              // 32768
    const int blocks = batch / ITEMS_PER_BLOCK;      // 1024

    tiny_transformer_kernel<<<blocks, THREADS>>>(x, embed, pos, blm, out);
}